// round 13
// baseline (speedup 1.0000x reference)
#include <cuda_runtime.h>
#include <cuda_bf16.h>
#include <cuda_fp16.h>
#include <math_constants.h>
#include <cstdint>

#define DIMC     384
#define NHEADS   12
#define HD       32
#define NTOK     49
#define NWIN     4096
#define MROWS    (NWIN * NTOK)   // 200704
#define QKV_N    (3 * DIMC)      // 1152
#define KDIM     384

// Scratch (device globals — no allocation allowed)
__device__ float  g_qkv[(size_t)MROWS * QKV_N];    // qkv intermediate (fp32)
__device__ __half g_xf [(size_t)MROWS * DIMC];     // x in fp16
__device__ __half g_qwf[(size_t)KDIM * QKV_N];     // qkv_w in fp16
__device__ __half g_af [(size_t)MROWS * DIMC];     // attn out in fp16
__device__ __half g_pwf[(size_t)KDIM * DIMC];      // proj_w in fp16
__device__ float  g_bias[NHEADS * NTOK * NTOK];    // expanded bias

// ---------------------------------------------------------------------------
// fp32 -> fp16 conversion (4 elems/thread)
__global__ void __launch_bounds__(256)
conv_f16(const float* __restrict__ in, __half* __restrict__ out, size_t n4)
{
    size_t i = (size_t)blockIdx.x * blockDim.x + threadIdx.x;
    if (i >= n4) return;
    float4 v = ((const float4*)in)[i];
    __half2* o = (__half2*)out;
    o[i * 2]     = __floats2half2_rn(v.x, v.y);
    o[i * 2 + 1] = __floats2half2_rn(v.z, v.w);
}

// Expand bias_table[rpi[nm]*12+h] -> g_bias[h][n][m]
__global__ void __launch_bounds__(256)
expand_bias(const float* __restrict__ bias_table, const int* __restrict__ rpi,
            float* __restrict__ out)
{
    int i = blockIdx.x * blockDim.x + threadIdx.x;
    if (i >= NHEADS * NTOK * NTOK) return;
    const int h = i / (NTOK * NTOK);
    const int nm = i - h * (NTOK * NTOK);
    out[i] = bias_table[rpi[nm] * NHEADS + h];
}

// ---------------------------------------------------------------------------
// FP16 tensor-core GEMM: C = A@B + bias (fp32 out).
// 3-stage cp.async, WAIT -> SYNC -> ISSUE -> COMPUTE, one barrier per slab.
// BM=128, BN=128, BK=32, 256 threads (2x4 warps), warp tile 64x32, 2 CTAs/SM,
// compile-time K=384 fully unrolled.
// ---------------------------------------------------------------------------
#define AST 40
#define BST 136
#define SA_ELEMS (128 * AST)
#define SB_ELEMS (32 * BST)
#define NSTAGE 3
#define NK (KDIM / 32)   // 12
#define STAGE_F16 (SA_ELEMS + SB_ELEMS)
#define GEMM_SMEM_F16 (NSTAGE * STAGE_F16 * 2)   // 56832 B

__device__ __forceinline__ uint32_t smem_u32(const void* p) {
    return (uint32_t)__cvta_generic_to_shared(p);
}
__device__ __forceinline__ void cp16(uint32_t dst, const void* src) {
    asm volatile("cp.async.cg.shared.global [%0], [%1], 16;" :: "r"(dst), "l"(src));
}
__device__ __forceinline__ void cp_commit() { asm volatile("cp.async.commit_group;"); }
__device__ __forceinline__ void cp_wait0()  { asm volatile("cp.async.wait_group 0;"); }
__device__ __forceinline__ void cp_wait1()  { asm volatile("cp.async.wait_group 1;"); }

__device__ __forceinline__ void ldsm_x4(unsigned* r, const void* p) {
    unsigned a = smem_u32(p);
    asm volatile("ldmatrix.sync.aligned.m8n8.x4.shared.b16 {%0,%1,%2,%3}, [%4];"
        : "=r"(r[0]), "=r"(r[1]), "=r"(r[2]), "=r"(r[3]) : "r"(a));
}
__device__ __forceinline__ void ldsm_x4_t(unsigned* r, const void* p) {
    unsigned a = smem_u32(p);
    asm volatile("ldmatrix.sync.aligned.m8n8.x4.trans.shared.b16 {%0,%1,%2,%3}, [%4];"
        : "=r"(r[0]), "=r"(r[1]), "=r"(r[2]), "=r"(r[3]) : "r"(a));
}
__device__ __forceinline__ void mma_f16(float* d, const unsigned* a, const unsigned* b) {
    asm volatile(
        "mma.sync.aligned.m16n8k16.row.col.f32.f16.f16.f32 "
        "{%0,%1,%2,%3}, {%4,%5,%6,%7}, {%8,%9}, {%0,%1,%2,%3};"
        : "+f"(d[0]), "+f"(d[1]), "+f"(d[2]), "+f"(d[3])
        : "r"(a[0]), "r"(a[1]), "r"(a[2]), "r"(a[3]), "r"(b[0]), "r"(b[1]));
}

__global__ void __launch_bounds__(256, 2)
gemm_f16(const __half* __restrict__ A, const __half* __restrict__ B,
         const float* __restrict__ bias, float* __restrict__ C,
         int M, int N)
{
    extern __shared__ __half smemh[];

    const int bm = blockIdx.y * 128;
    const int bn = blockIdx.x * 128;
    const int tid  = threadIdx.x;
    const int warp = tid >> 5;
    const int lane = tid & 31;
    const int wm = (warp >> 2) * 64;
    const int wn = (warp & 3)  * 32;

    const int ar0 = tid >> 2;
    const int ac  = (tid & 3) * 8;
    const int br0 = tid >> 4;
    const int bc  = (tid & 15) * 8;

    float acc[4][4][4] = {};

    auto issue = [&](int kt, int stage) {
        __half* dA = smemh + stage * STAGE_F16;
        #pragma unroll
        for (int rr = 0; rr < 2; rr++) {
            const int r = ar0 + rr * 64;
            cp16(smem_u32(&dA[r * AST + ac]), A + (size_t)(bm + r) * KDIM + kt + ac);
        }
        __half* dB = dA + SA_ELEMS;
        #pragma unroll
        for (int rr = 0; rr < 2; rr++) {
            const int r = br0 + rr * 16;
            cp16(smem_u32(&dB[r * BST + bc]), B + (size_t)(kt + r) * N + bn + bc);
        }
    };

    issue(0, 0); cp_commit();
    issue(32, 1); cp_commit();

    #pragma unroll
    for (int it = 0; it < NK; it++) {
        const int cur = it % NSTAGE;

        // per-thread completion of current stage, then publish + certify free
        if (it + 2 < NK) cp_wait1(); else cp_wait0();
        __syncthreads();
        if (it + 2 < NK) {
            issue((it + 2) * 32, (it + 2) % NSTAGE);
            cp_commit();
        }

        const __half* pA = smemh + cur * STAGE_F16;
        const __half* pB = pA + SA_ELEMS;

        #pragma unroll
        for (int ks = 0; ks < 32; ks += 16) {
            unsigned af[4][4], bf[2][4];
            const int ar  = lane & 15;
            const int akc = ks + ((lane >> 4) << 3);
            const int bkr = ks + (lane & 15);
            const int bcc = ((lane >> 4) << 3);

            #pragma unroll
            for (int mi = 0; mi < 4; mi++)
                ldsm_x4(af[mi], &pA[(wm + mi * 16 + ar) * AST + akc]);
            #pragma unroll
            for (int nb = 0; nb < 2; nb++)
                ldsm_x4_t(bf[nb], &pB[bkr * BST + wn + nb * 16 + bcc]);

            #pragma unroll
            for (int mi = 0; mi < 4; mi++)
                #pragma unroll
                for (int ni = 0; ni < 4; ni++)
                    mma_f16(acc[mi][ni], af[mi], &bf[ni >> 1][(ni & 1) * 2]);
        }
    }

    #pragma unroll
    for (int ni = 0; ni < 4; ni++) {
        const int col = bn + wn + ni * 8 + (lane & 3) * 2;
        const float bx = bias[col];
        const float by = bias[col + 1];
        #pragma unroll
        for (int mi = 0; mi < 4; mi++) {
            const int row = bm + wm + mi * 16 + (lane >> 2);
            float* a4 = acc[mi][ni];
            *(float2*)&C[(size_t)row * N + col] =
                make_float2(a4[0] + bx, a4[1] + by);
            *(float2*)&C[(size_t)(row + 8) * N + col] =
                make_float2(a4[2] + bx, a4[3] + by);
        }
    }
}

// ---------------------------------------------------------------------------
// Window attention: one block per (window, head), fused scores+softmax pass.
// fp32 qkv in, fp16 out.  Accumulator chains split for ILP.
// ---------------------------------------------------------------------------
__global__ void __launch_bounds__(256)
win_attn(const float* __restrict__ qkv, const float* __restrict__ biasx,
         __half* __restrict__ outf)
{
    const int b = blockIdx.x;
    const int h = blockIdx.y;
    const int tid = threadIdx.x;

    __shared__ float qs[NTOK][HD + 1];
    __shared__ float ks[NTOK][HD + 1];
    __shared__ float vs[NTOK][HD + 1];
    __shared__ float at[NTOK][NTOK + 1];

    const float scale = 0.17677669529663687f;

    for (int idx = tid; idx < NTOK * HD; idx += 256) {
        const int n = idx >> 5, d = idx & 31;
        const size_t base = ((size_t)b * NTOK + n) * QKV_N + h * HD + d;
        qs[n][d] = qkv[base] * scale;
        ks[n][d] = qkv[base + DIMC];
        vs[n][d] = qkv[base + 2 * DIMC];
    }
    __syncthreads();

    // Fused scores + bias + softmax: one warp per row n.
    // Dot products use 2 partial sums per target to halve chain latency.
    const int warp = tid >> 5, lane = tid & 31;
    const float* brow_base = biasx + (size_t)h * NTOK * NTOK;
    for (int n = warp; n < NTOK; n += 8) {
        const int m2 = lane + 32;
        float v1a = 0.f, v1b = 0.f, v2a = 0.f, v2b = 0.f;
        #pragma unroll
        for (int d = 0; d < HD / 2; d++) {
            const float qa = qs[n][d];
            const float qb = qs[n][d + HD / 2];
            v1a = fmaf(qa, ks[lane][d], v1a);
            v1b = fmaf(qb, ks[lane][d + HD / 2], v1b);
            if (m2 < NTOK) {
                v2a = fmaf(qa, ks[m2][d], v2a);
                v2b = fmaf(qb, ks[m2][d + HD / 2], v2b);
            }
        }
        const float* brow = brow_base + n * NTOK;
        float v1 = v1a + v1b + brow[lane];
        float v2 = (m2 < NTOK) ? v2a + v2b + brow[m2] : -CUDART_INF_F;
        float mx = fmaxf(v1, v2);
        #pragma unroll
        for (int o = 16; o; o >>= 1) mx = fmaxf(mx, __shfl_xor_sync(0xFFFFFFFFu, mx, o));
        float e1 = __expf(v1 - mx);
        float e2 = (m2 < NTOK) ? __expf(v2 - mx) : 0.f;
        float sm = e1 + e2;
        #pragma unroll
        for (int o = 16; o; o >>= 1) sm += __shfl_xor_sync(0xFFFFFFFFu, sm, o);
        const float inv = __frcp_rn(sm);
        at[n][lane] = e1 * inv;
        if (m2 < NTOK) at[n][m2] = e2 * inv;
    }
    __syncthreads();

    // out = attn @ v with 4 partial-sum chains (49 = 4*12 + 1)
    for (int idx = tid; idx < NTOK * HD; idx += 256) {
        const int n = idx >> 5, d = idx & 31;
        float s0 = 0.f, s1 = 0.f, s2 = 0.f, s3 = 0.f;
        #pragma unroll
        for (int m = 0; m < 48; m += 4) {
            s0 = fmaf(at[n][m],     vs[m][d],     s0);
            s1 = fmaf(at[n][m + 1], vs[m + 1][d], s1);
            s2 = fmaf(at[n][m + 2], vs[m + 2][d], s2);
            s3 = fmaf(at[n][m + 3], vs[m + 3][d], s3);
        }
        float s = (s0 + s1) + (s2 + s3) + at[n][48] * vs[48][d];
        outf[((size_t)b * NTOK + n) * DIMC + h * HD + d] = __float2half(s);
    }
}

// ---------------------------------------------------------------------------
extern "C" void kernel_launch(void* const* d_in, const int* in_sizes, int n_in,
                              void* d_out, int out_size)
{
    const float* x          = (const float*)d_in[0];
    const float* qkv_w      = (const float*)d_in[1];
    const float* qkv_b      = (const float*)d_in[2];
    const float* proj_w     = (const float*)d_in[3];
    const float* proj_b     = (const float*)d_in[4];
    const float* bias_table = (const float*)d_in[5];
    const int*   rpi        = (const int*)d_in[6];
    float* out = (float*)d_out;

    float *qkv, *biasx;
    __half *xf, *qwf, *af, *pwf;
    cudaGetSymbolAddress((void**)&qkv, g_qkv);
    cudaGetSymbolAddress((void**)&xf, g_xf);
    cudaGetSymbolAddress((void**)&qwf, g_qwf);
    cudaGetSymbolAddress((void**)&af, g_af);
    cudaGetSymbolAddress((void**)&pwf, g_pwf);
    cudaGetSymbolAddress((void**)&biasx, g_bias);

    cudaFuncSetAttribute(gemm_f16,
                         cudaFuncAttributeMaxDynamicSharedMemorySize, GEMM_SMEM_F16);

    // 0) conversions + bias expansion
    {
        size_t n4 = (size_t)MROWS * DIMC / 4;
        conv_f16<<<(unsigned)((n4 + 255) / 256), 256>>>(x, xf, n4);
        size_t w4 = (size_t)KDIM * QKV_N / 4;
        conv_f16<<<(unsigned)((w4 + 255) / 256), 256>>>(qkv_w, qwf, w4);
        size_t p4 = (size_t)KDIM * DIMC / 4;
        conv_f16<<<(unsigned)((p4 + 255) / 256), 256>>>(proj_w, pwf, p4);
        expand_bias<<<(NHEADS * NTOK * NTOK + 255) / 256, 256>>>(bias_table, rpi, biasx);
    }
    // 1) QKV GEMM (fp16 in, fp32 out)
    {
        dim3 grid(QKV_N / 128, MROWS / 128);
        gemm_f16<<<grid, 256, GEMM_SMEM_F16>>>(xf, qwf, qkv_b, qkv, MROWS, QKV_N);
    }
    // 2) Window attention (fp32 in, fp16 out)
    {
        dim3 grid(NWIN, NHEADS);
        win_attn<<<grid, 256>>>(qkv, biasx, af);
    }
    // 3) Proj GEMM (fp16 in, fp32 out)
    {
        dim3 grid(DIMC / 128, MROWS / 128);
        gemm_f16<<<grid, 256, GEMM_SMEM_F16>>>(af, pwf, proj_b, out, MROWS, DIMC);
    }
}

// round 14
// speedup vs baseline: 1.1592x; 1.1592x over previous
#include <cuda_runtime.h>
#include <cuda_bf16.h>
#include <cuda_fp16.h>
#include <math_constants.h>
#include <cstdint>

#define DIMC     384
#define NHEADS   12
#define HD       32
#define NTOK     49
#define NWIN     4096
#define MROWS    (NWIN * NTOK)   // 200704
#define QKV_N    (3 * DIMC)      // 1152
#define KDIM     384

// Scratch (device globals — no allocation allowed)
__device__ float  g_qkv[(size_t)MROWS * QKV_N];    // qkv intermediate (fp32)
__device__ __half g_xf [(size_t)MROWS * DIMC];     // x in fp16
__device__ __half g_qwf[(size_t)KDIM * QKV_N];     // qkv_w in fp16
__device__ __half g_af [(size_t)MROWS * DIMC];     // attn out in fp16
__device__ __half g_pwf[(size_t)KDIM * DIMC];      // proj_w in fp16
__device__ float  g_bias[NHEADS * NTOK * NTOK];    // expanded bias

// ---------------------------------------------------------------------------
// FFMA-only exp: exp(x) = 2^(x*log2e), round via float-magic, degree-5 poly.
// Avoids the MUFU pipe entirely (74 ops/cyc chip-wide vs 9472 FMA/cyc).
// Accurate to ~1e-7 relative on the post-max-subtraction range [-80, 0].
// ---------------------------------------------------------------------------
__device__ __forceinline__ float fast_exp(float x)
{
    x = fmaxf(x, -80.0f);                       // guard exponent underflow
    const float LOG2E = 1.4426950408889634f;
    const float MAGIC = 12582912.0f;            // 1.5 * 2^23
    float t  = fmaf(x, LOG2E, MAGIC);           // low bits hold round(x*log2e)
    int   ni = __float_as_int(t) - 0x4B400000;  // bits of MAGIC
    float n  = t - MAGIC;
    float f  = fmaf(x, LOG2E, -n);              // f in [-0.5, 0.5]
    // 2^f polynomial (Taylor in ln2, deg 5: max rel err ~2e-8 on the range)
    float p = 0.0013333558f;
    p = fmaf(p, f, 0.0096181291f);
    p = fmaf(p, f, 0.0555041087f);
    p = fmaf(p, f, 0.2402265070f);
    p = fmaf(p, f, 0.6931471806f);
    p = fmaf(p, f, 1.0f);
    return p * __int_as_float((ni + 127) << 23);
}

// fp32 -> fp16 conversion (4 elems/thread)
__global__ void __launch_bounds__(256)
conv_f16(const float* __restrict__ in, __half* __restrict__ out, size_t n4)
{
    size_t i = (size_t)blockIdx.x * blockDim.x + threadIdx.x;
    if (i >= n4) return;
    float4 v = ((const float4*)in)[i];
    __half2* o = (__half2*)out;
    o[i * 2]     = __floats2half2_rn(v.x, v.y);
    o[i * 2 + 1] = __floats2half2_rn(v.z, v.w);
}

// Expand bias_table[rpi[nm]*12+h] -> g_bias[h][n][m]
__global__ void __launch_bounds__(256)
expand_bias(const float* __restrict__ bias_table, const int* __restrict__ rpi,
            float* __restrict__ out)
{
    int i = blockIdx.x * blockDim.x + threadIdx.x;
    if (i >= NHEADS * NTOK * NTOK) return;
    const int h = i / (NTOK * NTOK);
    const int nm = i - h * (NTOK * NTOK);
    out[i] = bias_table[rpi[nm] * NHEADS + h];
}

// ---------------------------------------------------------------------------
// FP16 tensor-core GEMM: C = A@B + bias (fp32 out).
// 3-stage cp.async, WAIT -> SYNC -> ISSUE -> COMPUTE, one barrier per slab.
// BM=128, BN=128, BK=32, 256 threads (2x4 warps), warp tile 64x32, 2 CTAs/SM,
// compile-time K=384 fully unrolled.  (R10 winner, unchanged.)
// ---------------------------------------------------------------------------
#define AST 40
#define BST 136
#define SA_ELEMS (128 * AST)
#define SB_ELEMS (32 * BST)
#define NSTAGE 3
#define NK (KDIM / 32)   // 12
#define STAGE_F16 (SA_ELEMS + SB_ELEMS)
#define GEMM_SMEM_F16 (NSTAGE * STAGE_F16 * 2)   // 56832 B

__device__ __forceinline__ uint32_t smem_u32(const void* p) {
    return (uint32_t)__cvta_generic_to_shared(p);
}
__device__ __forceinline__ void cp16(uint32_t dst, const void* src) {
    asm volatile("cp.async.cg.shared.global [%0], [%1], 16;" :: "r"(dst), "l"(src));
}
__device__ __forceinline__ void cp_commit() { asm volatile("cp.async.commit_group;"); }
__device__ __forceinline__ void cp_wait0()  { asm volatile("cp.async.wait_group 0;"); }
__device__ __forceinline__ void cp_wait1()  { asm volatile("cp.async.wait_group 1;"); }

__device__ __forceinline__ void ldsm_x4(unsigned* r, const void* p) {
    unsigned a = smem_u32(p);
    asm volatile("ldmatrix.sync.aligned.m8n8.x4.shared.b16 {%0,%1,%2,%3}, [%4];"
        : "=r"(r[0]), "=r"(r[1]), "=r"(r[2]), "=r"(r[3]) : "r"(a));
}
__device__ __forceinline__ void ldsm_x4_t(unsigned* r, const void* p) {
    unsigned a = smem_u32(p);
    asm volatile("ldmatrix.sync.aligned.m8n8.x4.trans.shared.b16 {%0,%1,%2,%3}, [%4];"
        : "=r"(r[0]), "=r"(r[1]), "=r"(r[2]), "=r"(r[3]) : "r"(a));
}
__device__ __forceinline__ void mma_f16(float* d, const unsigned* a, const unsigned* b) {
    asm volatile(
        "mma.sync.aligned.m16n8k16.row.col.f32.f16.f16.f32 "
        "{%0,%1,%2,%3}, {%4,%5,%6,%7}, {%8,%9}, {%0,%1,%2,%3};"
        : "+f"(d[0]), "+f"(d[1]), "+f"(d[2]), "+f"(d[3])
        : "r"(a[0]), "r"(a[1]), "r"(a[2]), "r"(a[3]), "r"(b[0]), "r"(b[1]));
}

__global__ void __launch_bounds__(256, 2)
gemm_f16(const __half* __restrict__ A, const __half* __restrict__ B,
         const float* __restrict__ bias, float* __restrict__ C,
         int M, int N)
{
    extern __shared__ __half smemh[];

    const int bm = blockIdx.y * 128;
    const int bn = blockIdx.x * 128;
    const int tid  = threadIdx.x;
    const int warp = tid >> 5;
    const int lane = tid & 31;
    const int wm = (warp >> 2) * 64;
    const int wn = (warp & 3)  * 32;

    const int ar0 = tid >> 2;
    const int ac  = (tid & 3) * 8;
    const int br0 = tid >> 4;
    const int bc  = (tid & 15) * 8;

    float acc[4][4][4] = {};

    auto issue = [&](int kt, int stage) {
        __half* dA = smemh + stage * STAGE_F16;
        #pragma unroll
        for (int rr = 0; rr < 2; rr++) {
            const int r = ar0 + rr * 64;
            cp16(smem_u32(&dA[r * AST + ac]), A + (size_t)(bm + r) * KDIM + kt + ac);
        }
        __half* dB = dA + SA_ELEMS;
        #pragma unroll
        for (int rr = 0; rr < 2; rr++) {
            const int r = br0 + rr * 16;
            cp16(smem_u32(&dB[r * BST + bc]), B + (size_t)(kt + r) * N + bn + bc);
        }
    };

    issue(0, 0); cp_commit();
    issue(32, 1); cp_commit();

    #pragma unroll
    for (int it = 0; it < NK; it++) {
        const int cur = it % NSTAGE;

        // per-thread completion of current stage, then publish + certify free
        if (it + 2 < NK) cp_wait1(); else cp_wait0();
        __syncthreads();
        if (it + 2 < NK) {
            issue((it + 2) * 32, (it + 2) % NSTAGE);
            cp_commit();
        }

        const __half* pA = smemh + cur * STAGE_F16;
        const __half* pB = pA + SA_ELEMS;

        #pragma unroll
        for (int ks = 0; ks < 32; ks += 16) {
            unsigned af[4][4], bf[2][4];
            const int ar  = lane & 15;
            const int akc = ks + ((lane >> 4) << 3);
            const int bkr = ks + (lane & 15);
            const int bcc = ((lane >> 4) << 3);

            #pragma unroll
            for (int mi = 0; mi < 4; mi++)
                ldsm_x4(af[mi], &pA[(wm + mi * 16 + ar) * AST + akc]);
            #pragma unroll
            for (int nb = 0; nb < 2; nb++)
                ldsm_x4_t(bf[nb], &pB[bkr * BST + wn + nb * 16 + bcc]);

            #pragma unroll
            for (int mi = 0; mi < 4; mi++)
                #pragma unroll
                for (int ni = 0; ni < 4; ni++)
                    mma_f16(acc[mi][ni], af[mi], &bf[ni >> 1][(ni & 1) * 2]);
        }
    }

    #pragma unroll
    for (int ni = 0; ni < 4; ni++) {
        const int col = bn + wn + ni * 8 + (lane & 3) * 2;
        const float bx = bias[col];
        const float by = bias[col + 1];
        #pragma unroll
        for (int mi = 0; mi < 4; mi++) {
            const int row = bm + wm + mi * 16 + (lane >> 2);
            float* a4 = acc[mi][ni];
            *(float2*)&C[(size_t)row * N + col] =
                make_float2(a4[0] + bx, a4[1] + by);
            *(float2*)&C[(size_t)(row + 8) * N + col] =
                make_float2(a4[2] + bx, a4[3] + by);
        }
    }
}

// ---------------------------------------------------------------------------
// Window attention: one block per (window, head), fused scores+softmax pass.
// Exact R10 structure (simple accumulation chains); only __expf -> fast_exp.
// ---------------------------------------------------------------------------
__global__ void __launch_bounds__(256)
win_attn(const float* __restrict__ qkv, const float* __restrict__ biasx,
         __half* __restrict__ outf)
{
    const int b = blockIdx.x;
    const int h = blockIdx.y;
    const int tid = threadIdx.x;

    __shared__ float qs[NTOK][HD + 1];
    __shared__ float ks[NTOK][HD + 1];
    __shared__ float vs[NTOK][HD + 1];
    __shared__ float at[NTOK][NTOK + 1];

    const float scale = 0.17677669529663687f;

    for (int idx = tid; idx < NTOK * HD; idx += 256) {
        const int n = idx >> 5, d = idx & 31;
        const size_t base = ((size_t)b * NTOK + n) * QKV_N + h * HD + d;
        qs[n][d] = qkv[base] * scale;
        ks[n][d] = qkv[base + DIMC];
        vs[n][d] = qkv[base + 2 * DIMC];
    }
    __syncthreads();

    const int warp = tid >> 5, lane = tid & 31;
    const float* brow_base = biasx + (size_t)h * NTOK * NTOK;
    for (int n = warp; n < NTOK; n += 8) {
        const int m2 = lane + 32;
        float v1 = 0.f, v2 = 0.f;
        #pragma unroll
        for (int d = 0; d < HD; d++) {
            const float q = qs[n][d];
            v1 = fmaf(q, ks[lane][d], v1);
            if (m2 < NTOK) v2 = fmaf(q, ks[m2][d], v2);
        }
        const float* brow = brow_base + n * NTOK;
        v1 += brow[lane];
        v2 = (m2 < NTOK) ? v2 + brow[m2] : -CUDART_INF_F;
        float mx = fmaxf(v1, v2);
        #pragma unroll
        for (int o = 16; o; o >>= 1) mx = fmaxf(mx, __shfl_xor_sync(0xFFFFFFFFu, mx, o));
        float e1 = fast_exp(v1 - mx);
        float e2 = (m2 < NTOK) ? fast_exp(v2 - mx) : 0.f;
        float sm = e1 + e2;
        #pragma unroll
        for (int o = 16; o; o >>= 1) sm += __shfl_xor_sync(0xFFFFFFFFu, sm, o);
        const float inv = __frcp_rn(sm);
        at[n][lane] = e1 * inv;
        if (m2 < NTOK) at[n][m2] = e2 * inv;
    }
    __syncthreads();

    for (int idx = tid; idx < NTOK * HD; idx += 256) {
        const int n = idx >> 5, d = idx & 31;
        float s = 0.f;
        #pragma unroll
        for (int m = 0; m < NTOK; m++) s = fmaf(at[n][m], vs[m][d], s);
        outf[((size_t)b * NTOK + n) * DIMC + h * HD + d] = __float2half(s);
    }
}

// ---------------------------------------------------------------------------
extern "C" void kernel_launch(void* const* d_in, const int* in_sizes, int n_in,
                              void* d_out, int out_size)
{
    const float* x          = (const float*)d_in[0];
    const float* qkv_w      = (const float*)d_in[1];
    const float* qkv_b      = (const float*)d_in[2];
    const float* proj_w     = (const float*)d_in[3];
    const float* proj_b     = (const float*)d_in[4];
    const float* bias_table = (const float*)d_in[5];
    const int*   rpi        = (const int*)d_in[6];
    float* out = (float*)d_out;

    float *qkv, *biasx;
    __half *xf, *qwf, *af, *pwf;
    cudaGetSymbolAddress((void**)&qkv, g_qkv);
    cudaGetSymbolAddress((void**)&xf, g_xf);
    cudaGetSymbolAddress((void**)&qwf, g_qwf);
    cudaGetSymbolAddress((void**)&af, g_af);
    cudaGetSymbolAddress((void**)&pwf, g_pwf);
    cudaGetSymbolAddress((void**)&biasx, g_bias);

    cudaFuncSetAttribute(gemm_f16,
                         cudaFuncAttributeMaxDynamicSharedMemorySize, GEMM_SMEM_F16);

    // 0) conversions + bias expansion
    {
        size_t n4 = (size_t)MROWS * DIMC / 4;
        conv_f16<<<(unsigned)((n4 + 255) / 256), 256>>>(x, xf, n4);
        size_t w4 = (size_t)KDIM * QKV_N / 4;
        conv_f16<<<(unsigned)((w4 + 255) / 256), 256>>>(qkv_w, qwf, w4);
        size_t p4 = (size_t)KDIM * DIMC / 4;
        conv_f16<<<(unsigned)((p4 + 255) / 256), 256>>>(proj_w, pwf, p4);
        expand_bias<<<(NHEADS * NTOK * NTOK + 255) / 256, 256>>>(bias_table, rpi, biasx);
    }
    // 1) QKV GEMM (fp16 in, fp32 out)
    {
        dim3 grid(QKV_N / 128, MROWS / 128);
        gemm_f16<<<grid, 256, GEMM_SMEM_F16>>>(xf, qwf, qkv_b, qkv, MROWS, QKV_N);
    }
    // 2) Window attention (fp32 in, fp16 out)
    {
        dim3 grid(NWIN, NHEADS);
        win_attn<<<grid, 256>>>(qkv, biasx, af);
    }
    // 3) Proj GEMM (fp16 in, fp32 out)
    {
        dim3 grid(DIMC / 128, MROWS / 128);
        gemm_f16<<<grid, 256, GEMM_SMEM_F16>>>(af, pwf, proj_b, out, MROWS, DIMC);
    }
}